// round 17
// baseline (speedup 1.0000x reference)
#include <cuda_runtime.h>
#include <cuda_bf16.h>
#include <cstdint>
#include <cstddef>

#define BB 4
#define CC 256
#define C2 128
#define NN 4096
#define NTILES 32   // NN / 128
#define NCH 32      // n-chunks of 128 (full N, no split)
#define SK 40       // smem tile row stride in halves (80 B)
#define OTS 136     // smem output tile row stride in halves (kproj epilogue)

// Fused-kernel smem layout (bytes within dynamic smem):
#define TH_OFF 0        // theta  [128 m][128 k] as 4 SK-subtiles (40960)
#define PH_OFF 40960    // phi    chunk, same shape (40960)
#define GG_OFF 81920    // g      chunk [128 c][128 n] as 4 SK-subtiles (40960)
#define WT_OFF 122880   // W=exp(S) [128 m][128 n] as 4 SK-subtiles (40960)
#define DSM_BYTES 163840

// ---------------------------------------------------------------------------
// Scratch (static __device__ globals)
// ---------------------------------------------------------------------------
__device__ __nv_bfloat16 g_theta_t[(size_t)BB * NN * C2];     // [b][m][k] k-contig
__device__ __nv_bfloat16 g_phi_t  [(size_t)BB * NN * C2];     // [b][n][k] k-contig
__device__ __nv_bfloat16 g_gq     [(size_t)BB * C2 * NN];     // [b][c][n] n-contig
__device__ __nv_bfloat16 g_wcat   [3 * C2 * CC];              // bf16 weights [p][o][c]
__device__ __nv_bfloat16 g_wo16   [CC * C2];                  // bf16 w_out [o][c]
__device__ __nv_bfloat16 g_xt     [(size_t)BB * NN * CC];     // x^T bf16 [b][n][c]
__device__ __nv_bfloat16 g_obt    [(size_t)BB * NN * C2];     // normalized attn-out [b][m][c]

// ---------------------------------------------------------------------------
// Helpers: ldmatrix + mma.sync + cp.async (all legal at plain sm_103)
// ---------------------------------------------------------------------------
__device__ __forceinline__ uint32_t smem_u32(const void* p) {
    uint32_t a;
    asm("{ .reg .u64 t; cvta.to.shared.u64 t, %1; cvt.u32.u64 %0, t; }"
        : "=r"(a) : "l"(p));
    return a;
}
__device__ __forceinline__ void ldsm4(uint32_t* r, uint32_t addr) {
    asm volatile("ldmatrix.sync.aligned.m8n8.x4.shared.b16 {%0,%1,%2,%3}, [%4];"
                 : "=r"(r[0]), "=r"(r[1]), "=r"(r[2]), "=r"(r[3]) : "r"(addr));
}
__device__ __forceinline__ void mma_bf16(float* c, const uint32_t* a, const uint32_t* b) {
    asm volatile("mma.sync.aligned.m16n8k16.row.col.f32.bf16.bf16.f32 "
                 "{%0,%1,%2,%3}, {%4,%5,%6,%7}, {%8,%9}, {%0,%1,%2,%3};"
                 : "+f"(c[0]), "+f"(c[1]), "+f"(c[2]), "+f"(c[3])
                 : "r"(a[0]), "r"(a[1]), "r"(a[2]), "r"(a[3]),
                   "r"(b[0]), "r"(b[1]));
}
__device__ __forceinline__ void cp16(uint32_t dst, const void* src) {
    asm volatile("cp.async.cg.shared.global [%0], [%1], 16;"
                 :: "r"(dst), "l"(src) : "memory");
}
#define CP_COMMIT() asm volatile("cp.async.commit_group;" ::: "memory")
template <int N> __device__ __forceinline__ void cp_wait() {
    asm volatile("cp.async.wait_group %0;" :: "n"(N) : "memory");
}

// ---------------------------------------------------------------------------
// P0: projection weights -> bf16 [p][o][c];  P0b: w_out -> bf16
// ---------------------------------------------------------------------------
__global__ __launch_bounds__(256) void kprep_w(
    const float* __restrict__ wt, const float* __restrict__ wp,
    const float* __restrict__ wg)
{
    const int i = blockIdx.x * 256 + threadIdx.x;
    const int p = i >> 15, r = i & 32767;
    const float* W = (p == 0) ? wt : (p == 1) ? wp : wg;
    g_wcat[i] = __float2bfloat16(W[r]);
}
__global__ __launch_bounds__(256) void kprep_wo(const float* __restrict__ wo)
{
    const int i = blockIdx.x * 256 + threadIdx.x;
    g_wo16[i] = __float2bfloat16(wo[i]);
}

// ---------------------------------------------------------------------------
// P1: transpose x [b][c][n] fp32 -> x^T [b][n][c] bf16
// ---------------------------------------------------------------------------
__global__ __launch_bounds__(256) void kprep_x(const float* __restrict__ x)
{
    __shared__ float t[32][33];
    const int b = blockIdx.z, c0 = blockIdx.y * 32, n0 = blockIdx.x * 32;
    const int tx = threadIdx.x & 31, ty = threadIdx.x >> 5;
    const float* X = x + ((size_t)b * CC + c0) * NN + n0;
    #pragma unroll
    for (int r = 0; r < 32; r += 8)
        t[ty + r][tx] = X[(size_t)(ty + r) * NN + tx];
    __syncthreads();
    __nv_bfloat16* XT = g_xt + ((size_t)b * NN + n0) * CC + c0;
    #pragma unroll
    for (int r = 0; r < 32; r += 8)
        XT[(size_t)(ty + r) * CC + tx] = __float2bfloat16(t[tx][ty + r]);
}

// ---------------------------------------------------------------------------
// K1: projections via mma.sync (register-prefetch double buffer).
//   p=0 -> theta_t [n][o], p=1 -> phi_t [n][o], p=2 -> gq [o][n]
// ---------------------------------------------------------------------------
__global__ __launch_bounds__(256) void kproj_m(
    const float* __restrict__ bt, const float* __restrict__ bp,
    const float* __restrict__ bg)
{
    __shared__ __align__(16) char raw[40960];

    const int b  = blockIdx.z;
    const int p  = blockIdx.y;
    const int nb = blockIdx.x * 128;
    const int tid  = threadIdx.x;
    const int lane = tid & 31, wid = tid >> 5;
    const int wm = (wid & 1) * 64, wn = (wid >> 1) * 32;

    const int la = lane & 7, lb = (lane >> 3) & 1, lc = lane >> 4;
    const int rowA = la + lb * 8, colA = lc * 8;
    const int rowB = la + lc * 8, colB = lb * 8;

    const int grow = tid >> 1, ghalf = (tid & 1) * 16;
    const __nv_bfloat16* aSrc = g_wcat + ((size_t)p * C2 + grow) * CC + ghalf;
    const __nv_bfloat16* bSrc = g_xt + ((size_t)b * NN + nb + grow) * CC + ghalf;
    const int sOff = (grow * SK + ghalf) * 2;

    float acc[4][4][4];
    #pragma unroll
    for (int i = 0; i < 4; i++)
        #pragma unroll
        for (int j = 0; j < 4; j++)
            #pragma unroll
            for (int e = 0; e < 4; e++) acc[i][j][e] = 0.0f;

    *reinterpret_cast<uint4*>(raw + sOff) = *reinterpret_cast<const uint4*>(aSrc);
    *reinterpret_cast<uint4*>(raw + sOff + 16) = *reinterpret_cast<const uint4*>(aSrc + 8);
    *reinterpret_cast<uint4*>(raw + 20480 + sOff) = *reinterpret_cast<const uint4*>(bSrc);
    *reinterpret_cast<uint4*>(raw + 20480 + sOff + 16) = *reinterpret_cast<const uint4*>(bSrc + 8);
    __syncthreads();

    #pragma unroll
    for (int kc = 0; kc < 8; kc++) {
        const int cur = kc & 1;
        uint4 pa0, pa1, pb0, pb1;
        if (kc < 7) {
            const int k0 = (kc + 1) * 32;
            pa0 = *reinterpret_cast<const uint4*>(aSrc + k0);
            pa1 = *reinterpret_cast<const uint4*>(aSrc + k0 + 8);
            pb0 = *reinterpret_cast<const uint4*>(bSrc + k0);
            pb1 = *reinterpret_cast<const uint4*>(bSrc + k0 + 8);
        }
        const uint32_t aBase = smem_u32(raw + cur * 10240);
        const uint32_t bBase = smem_u32(raw + 20480 + cur * 10240);
        #pragma unroll
        for (int ks = 0; ks < 2; ks++) {
            uint32_t af[4][4], bf[4][2];
            #pragma unroll
            for (int fm = 0; fm < 4; fm++)
                ldsm4(af[fm], aBase +
                      (uint32_t)(((wm + fm * 16 + rowA) * SK + ks * 16 + colA) * 2));
            #pragma unroll
            for (int fp = 0; fp < 2; fp++) {
                uint32_t r[4];
                ldsm4(r, bBase +
                      (uint32_t)(((wn + fp * 16 + rowB) * SK + ks * 16 + colB) * 2));
                bf[fp * 2][0] = r[0]; bf[fp * 2][1] = r[1];
                bf[fp * 2 + 1][0] = r[2]; bf[fp * 2 + 1][1] = r[3];
            }
            #pragma unroll
            for (int fm = 0; fm < 4; fm++)
                #pragma unroll
                for (int fn = 0; fn < 4; fn++)
                    mma_bf16(acc[fm][fn], af[fm], bf[fn]);
        }
        if (kc < 7) {
            const int nxt = 1 - cur;
            *reinterpret_cast<uint4*>(raw + nxt * 10240 + sOff) = pa0;
            *reinterpret_cast<uint4*>(raw + nxt * 10240 + sOff + 16) = pa1;
            *reinterpret_cast<uint4*>(raw + 20480 + nxt * 10240 + sOff) = pb0;
            *reinterpret_cast<uint4*>(raw + 20480 + nxt * 10240 + sOff + 16) = pb1;
        }
        __syncthreads();
    }

    __nv_bfloat16* sOut = reinterpret_cast<__nv_bfloat16*>(raw);
    const float* Bias = (p == 0) ? bt : (p == 1) ? bp : bg;
    const int tq = lane & 3, tr = lane >> 2;
    #pragma unroll
    for (int fm = 0; fm < 4; fm++) {
        const int o0 = wm + fm * 16 + tr;
        const int o1 = o0 + 8;
        const float b0 = Bias[o0], b1 = Bias[o1];
        #pragma unroll
        for (int fn = 0; fn < 4; fn++) {
            const int n = wn + fn * 8 + tq * 2;
            *reinterpret_cast<__nv_bfloat162*>(sOut + o0 * OTS + n) =
                __floats2bfloat162_rn(acc[fm][fn][0] + b0, acc[fm][fn][1] + b0);
            *reinterpret_cast<__nv_bfloat162*>(sOut + o1 * OTS + n) =
                __floats2bfloat162_rn(acc[fm][fn][2] + b1, acc[fm][fn][3] + b1);
        }
    }
    __syncthreads();

    if (p == 2) {
        const int r = tid >> 1, h = (tid & 1) * 64;
        const __nv_bfloat16* srcRow = sOut + r * OTS + h;
        __nv_bfloat16* dst = g_gq + ((size_t)b * C2 + r) * NN + nb + h;
        #pragma unroll
        for (int q = 0; q < 8; q++)
            *reinterpret_cast<uint4*>(dst + q * 8) =
                *reinterpret_cast<const uint4*>(srcRow + q * 8);
    } else {
        __nv_bfloat16* T = (p == 0 ? g_theta_t : g_phi_t) + (size_t)b * NN * C2;
        const int n = tid >> 1, h = (tid & 1) * 64;
        __nv_bfloat16* dst = T + ((size_t)(nb + n)) * C2 + h;
        #pragma unroll
        for (int q = 0; q < 8; q++) {
            __nv_bfloat16 v[8];
            #pragma unroll
            for (int j = 0; j < 8; j++) v[j] = sOut[(h + q * 8 + j) * OTS + n];
            *reinterpret_cast<uint4*>(dst + q * 8) = *reinterpret_cast<uint4*>(v);
        }
    }
}

// ---------------------------------------------------------------------------
// K2 (fully fused): one CTA per (b, m-tile). 32 n-chunks of 128:
//   GEMM1 S = theta . phi^T -> W = exp(S) (bf16, smem only)
//   GEMM2 D[m][c] += W . g^T        (A = W, B = g)
// Row sums -> in-kernel softmax normalization -> bf16 obt[b][m][c] direct.
// No partials, no ktr, no kcomb.
// ---------------------------------------------------------------------------
__global__ __launch_bounds__(256) void kfa2()
{
    extern __shared__ __align__(16) char dsm[];
    __shared__ float wsm[4][128];
    __shared__ float stot[128];

    const int b  = blockIdx.y;
    const int mb = blockIdx.x * 128;
    const int tid  = threadIdx.x;
    const int lane = tid & 31, wid = tid >> 5;
    const int wm = (wid & 1) * 64, wn = (wid >> 1) * 32;
    const int ng = wid >> 1;

    const int la = lane & 7, lb = (lane >> 3) & 1, lc = lane >> 4;
    const int rowA = la + lb * 8, colA = lc * 8;
    const int rowB = la + lc * 8, colB = lb * 8;

    const uint32_t su = smem_u32(dsm);
    const int grow = tid >> 1;            // tile row this thread stages
    const int hbase = (tid & 1) * 64;     // first of 64 halves it stages

    const __nv_bfloat16* thRow = g_theta_t + ((size_t)b * NN + mb + grow) * C2;
    const __nv_bfloat16* phRow = g_phi_t + ((size_t)b * NN + grow) * C2;
    const __nv_bfloat16* gRow  = g_gq + ((size_t)b * C2 + grow) * NN;

    // Stage one 128x128-half tile: 8 x cp16 (8 halves each) per thread.
    auto load_tile = [&](uint32_t dstBase, const __nv_bfloat16* rowPtr) {
        #pragma unroll
        for (int q = 0; q < 8; q++) {
            const int hc = hbase + q * 8;
            cp16(su + dstBase + (uint32_t)((hc >> 5) * 10240 +
                 (grow * SK + (hc & 31)) * 2), rowPtr + hc);
        }
    };

    float acc2[4][4][4];
    float rs0[4], rs1[4];
    #pragma unroll
    for (int i = 0; i < 4; i++) {
        rs0[i] = 0.0f; rs1[i] = 0.0f;
        #pragma unroll
        for (int j = 0; j < 4; j++)
            #pragma unroll
            for (int e = 0; e < 4; e++) acc2[i][j][e] = 0.0f;
    }

    // Prologue: theta + phi_0 as one group; g_0 as a second group.
    load_tile(TH_OFF, thRow);
    load_tile(PH_OFF, phRow);
    CP_COMMIT();
    load_tile(GG_OFF, gRow);
    CP_COMMIT();

    const int tq = lane & 3, tr = lane >> 2;

    for (int ch = 0; ch < NCH; ch++) {
        cp_wait<1>();            // phi_ch (and theta on ch 0) resident
        __syncthreads();

        // ---- GEMM1: S[m][n] = theta . phi^T over K=128
        float acc1[4][4][4];
        #pragma unroll
        for (int i = 0; i < 4; i++)
            #pragma unroll
            for (int j = 0; j < 4; j++)
                #pragma unroll
                for (int e = 0; e < 4; e++) acc1[i][j][e] = 0.0f;

        #pragma unroll
        for (int kk = 0; kk < 4; kk++) {
            const uint32_t aBase = su + TH_OFF + kk * 10240;
            const uint32_t bBase = su + PH_OFF + kk * 10240;
            #pragma unroll
            for (int ks = 0; ks < 2; ks++) {
                uint32_t af[4][4], bf[4][2];
                #pragma unroll
                for (int fm = 0; fm < 4; fm++)
                    ldsm4(af[fm], aBase +
                          (uint32_t)(((wm + fm * 16 + rowA) * SK + ks * 16 + colA) * 2));
                #pragma unroll
                for (int fp = 0; fp < 2; fp++) {
                    uint32_t r[4];
                    ldsm4(r, bBase +
                          (uint32_t)(((wn + fp * 16 + rowB) * SK + ks * 16 + colB) * 2));
                    bf[fp * 2][0] = r[0]; bf[fp * 2][1] = r[1];
                    bf[fp * 2 + 1][0] = r[2]; bf[fp * 2 + 1][1] = r[3];
                }
                #pragma unroll
                for (int fm = 0; fm < 4; fm++)
                    #pragma unroll
                    for (int fn = 0; fn < 4; fn++)
                        mma_bf16(acc1[fm][fn], af[fm], bf[fn]);
            }
        }
        __syncthreads();          // all warps done reading PH

        if (ch < NCH - 1) {       // prefetch phi_{ch+1}
            load_tile(PH_OFF, phRow + (size_t)(ch + 1) * 128 * C2);
            CP_COMMIT();
        }

        // ---- exp -> W subtiles in smem + accumulate row sums
        #pragma unroll
        for (int fm = 0; fm < 4; fm++) {
            const int r0 = wm + fm * 16 + tr;
            const int r1 = r0 + 8;
            float s0 = 0.0f, s1 = 0.0f;
            #pragma unroll
            for (int fn = 0; fn < 4; fn++) {
                float e00 = __expf(acc1[fm][fn][0]);
                float e01 = __expf(acc1[fm][fn][1]);
                float e10 = __expf(acc1[fm][fn][2]);
                float e11 = __expf(acc1[fm][fn][3]);
                s0 += e00 + e01;
                s1 += e10 + e11;
                const int n = wn + fn * 8 + tq * 2;        // 0..127 in chunk
                const uint32_t sub = (uint32_t)(n >> 5) * 10240;
                const int col = n & 31;
                *reinterpret_cast<__nv_bfloat162*>(dsm + WT_OFF + sub +
                    (r0 * SK + col) * 2) = __floats2bfloat162_rn(e00, e01);
                *reinterpret_cast<__nv_bfloat162*>(dsm + WT_OFF + sub +
                    (r1 * SK + col) * 2) = __floats2bfloat162_rn(e10, e11);
            }
            rs0[fm] += s0;
            rs1[fm] += s1;
        }

        if (ch < NCH - 1) cp_wait<1>(); else cp_wait<0>();  // g_ch resident
        __syncthreads();          // W stores visible + g ready

        // ---- GEMM2: D[m][c] += W . g^T (A = W rows m, B = g rows c, K = n)
        #pragma unroll
        for (int kk = 0; kk < 4; kk++) {
            const uint32_t aBase = su + WT_OFF + kk * 10240;
            const uint32_t bBase = su + GG_OFF + kk * 10240;
            #pragma unroll
            for (int ks = 0; ks < 2; ks++) {
                uint32_t af[4][4], bf[4][2];
                #pragma unroll
                for (int fm = 0; fm < 4; fm++)
                    ldsm4(af[fm], aBase +
                          (uint32_t)(((wm + fm * 16 + rowA) * SK + ks * 16 + colA) * 2));
                #pragma unroll
                for (int fp = 0; fp < 2; fp++) {
                    uint32_t r[4];
                    ldsm4(r, bBase +
                          (uint32_t)(((wn + fp * 16 + rowB) * SK + ks * 16 + colB) * 2));
                    bf[fp * 2][0] = r[0]; bf[fp * 2][1] = r[1];
                    bf[fp * 2 + 1][0] = r[2]; bf[fp * 2 + 1][1] = r[3];
                }
                #pragma unroll
                for (int fm = 0; fm < 4; fm++)
                    #pragma unroll
                    for (int fn = 0; fn < 4; fn++)
                        mma_bf16(acc2[fm][fn], af[fm], bf[fn]);
            }
        }
        __syncthreads();          // done reading GG and WT

        if (ch < NCH - 1) {       // prefetch g_{ch+1}
            load_tile(GG_OFF, gRow + (ch + 1) * 128);
            CP_COMMIT();
        }
    }

    // ---- full row sums: quad-reduce -> per-warp-group stage -> total
    #pragma unroll
    for (int fm = 0; fm < 4; fm++) {
        const int r0 = wm + fm * 16 + tr;
        const int r1 = r0 + 8;
        float s0 = rs0[fm], s1 = rs1[fm];
        #pragma unroll
        for (int off = 1; off < 4; off <<= 1) {
            s0 += __shfl_xor_sync(0xffffffffu, s0, off);
            s1 += __shfl_xor_sync(0xffffffffu, s1, off);
        }
        if (tq == 0) { wsm[ng][r0] = s0; wsm[ng][r1] = s1; }
    }
    __syncthreads();
    if (tid < 128)
        stot[tid] = 1.0f / (wsm[0][tid] + wsm[1][tid] + wsm[2][tid] + wsm[3][tid]);
    __syncthreads();

    // ---- normalize + store obt[b][mb+m][c] (bf162 per pair)
    __nv_bfloat16* OT = g_obt + ((size_t)b * NN + mb) * C2;
    #pragma unroll
    for (int fm = 0; fm < 4; fm++) {
        const int r0 = wm + fm * 16 + tr;
        const int r1 = r0 + 8;
        const float ri0 = stot[r0], ri1 = stot[r1];
        #pragma unroll
        for (int fn = 0; fn < 4; fn++) {
            const int c = wn + fn * 8 + tq * 2;
            *reinterpret_cast<__nv_bfloat162*>(OT + (size_t)r0 * C2 + c) =
                __floats2bfloat162_rn(acc2[fm][fn][0] * ri0, acc2[fm][fn][1] * ri0);
            *reinterpret_cast<__nv_bfloat162*>(OT + (size_t)r1 * C2 + c) =
                __floats2bfloat162_rn(acc2[fm][fn][2] * ri1, acc2[fm][fn][3] * ri1);
        }
    }
}

// ---------------------------------------------------------------------------
// K5: output projection via mma.sync + residual.
// ---------------------------------------------------------------------------
__global__ __launch_bounds__(256) void kfinal_m(
    const float* __restrict__ x, const float* __restrict__ bo,
    float* __restrict__ y)
{
    __shared__ __nv_bfloat16 sA[2][128 * SK];
    __shared__ __nv_bfloat16 sB[2][128 * SK];

    const int b  = blockIdx.z;
    const int ob = blockIdx.y * 128;
    const int mb = blockIdx.x * 128;
    const int tid  = threadIdx.x;
    const int lane = tid & 31, wid = tid >> 5;
    const int wm = (wid & 1) * 64, wn = (wid >> 1) * 32;

    const int la = lane & 7, lb = (lane >> 3) & 1, lc = lane >> 4;
    const int rowA = la + lb * 8, colA = lc * 8;
    const int rowB = la + lc * 8, colB = lb * 8;

    const int grow = tid >> 1, ghalf = (tid & 1) * 16;
    const __nv_bfloat16* aSrc = g_wo16 + ((size_t)(ob + grow)) * C2 + ghalf;
    const __nv_bfloat16* bSrc = g_obt + ((size_t)b * NN + mb + grow) * C2 + ghalf;
    const int sIdx = grow * SK + ghalf;

    float acc[4][4][4];
    #pragma unroll
    for (int i = 0; i < 4; i++)
        #pragma unroll
        for (int j = 0; j < 4; j++)
            #pragma unroll
            for (int e = 0; e < 4; e++) acc[i][j][e] = 0.0f;

    {
        uint4 a0 = *reinterpret_cast<const uint4*>(aSrc);
        uint4 a1 = *reinterpret_cast<const uint4*>(aSrc + 8);
        uint4 b0 = *reinterpret_cast<const uint4*>(bSrc);
        uint4 b1 = *reinterpret_cast<const uint4*>(bSrc + 8);
        *reinterpret_cast<uint4*>(&sA[0][sIdx])     = a0;
        *reinterpret_cast<uint4*>(&sA[0][sIdx + 8]) = a1;
        *reinterpret_cast<uint4*>(&sB[0][sIdx])     = b0;
        *reinterpret_cast<uint4*>(&sB[0][sIdx + 8]) = b1;
    }
    __syncthreads();

    #pragma unroll
    for (int kc = 0; kc < 4; kc++) {
        const int cur = kc & 1;
        uint4 pa0, pa1, pb0, pb1;
        if (kc < 3) {
            const int k0 = (kc + 1) * 32;
            pa0 = *reinterpret_cast<const uint4*>(aSrc + k0);
            pa1 = *reinterpret_cast<const uint4*>(aSrc + k0 + 8);
            pb0 = *reinterpret_cast<const uint4*>(bSrc + k0);
            pb1 = *reinterpret_cast<const uint4*>(bSrc + k0 + 8);
        }
        const uint32_t aBase = smem_u32(sA[cur]);
        const uint32_t bBase = smem_u32(sB[cur]);
        #pragma unroll
        for (int ks = 0; ks < 2; ks++) {
            uint32_t af[4][4], bf[4][2];
            #pragma unroll
            for (int fm = 0; fm < 4; fm++)
                ldsm4(af[fm], aBase +
                      (uint32_t)(((wm + fm * 16 + rowA) * SK + ks * 16 + colA) * 2));
            #pragma unroll
            for (int fp = 0; fp < 2; fp++) {
                uint32_t r[4];
                ldsm4(r, bBase +
                      (uint32_t)(((wn + fp * 16 + rowB) * SK + ks * 16 + colB) * 2));
                bf[fp * 2][0] = r[0]; bf[fp * 2][1] = r[1];
                bf[fp * 2 + 1][0] = r[2]; bf[fp * 2 + 1][1] = r[3];
            }
            #pragma unroll
            for (int fm = 0; fm < 4; fm++)
                #pragma unroll
                for (int fn = 0; fn < 4; fn++)
                    mma_bf16(acc[fm][fn], af[fm], bf[fn]);
        }
        if (kc < 3) {
            const int nxt = 1 - cur;
            *reinterpret_cast<uint4*>(&sA[nxt][sIdx])     = pa0;
            *reinterpret_cast<uint4*>(&sA[nxt][sIdx + 8]) = pa1;
            *reinterpret_cast<uint4*>(&sB[nxt][sIdx])     = pb0;
            *reinterpret_cast<uint4*>(&sB[nxt][sIdx + 8]) = pb1;
        }
        __syncthreads();
    }

    const int tq = lane & 3, tr = lane >> 2;
    #pragma unroll
    for (int fm = 0; fm < 4; fm++) {
        const int o0 = ob + wm + fm * 16 + tr;
        const int o1 = o0 + 8;
        const float bias0 = bo[o0], bias1 = bo[o1];
        #pragma unroll
        for (int fn = 0; fn < 4; fn++) {
            const int mc = mb + wn + fn * 8 + tq * 2;
            const size_t i0 = ((size_t)b * CC + o0) * NN + mc;
            const size_t i1 = ((size_t)b * CC + o1) * NN + mc;
            const float2 x0 = *reinterpret_cast<const float2*>(&x[i0]);
            const float2 x1 = *reinterpret_cast<const float2*>(&x[i1]);
            *reinterpret_cast<float2*>(&y[i0]) =
                make_float2(acc[fm][fn][0] + bias0 + x0.x,
                            acc[fm][fn][1] + bias0 + x0.y);
            *reinterpret_cast<float2*>(&y[i1]) =
                make_float2(acc[fm][fn][2] + bias1 + x1.x,
                            acc[fm][fn][3] + bias1 + x1.y);
        }
    }
}

// ---------------------------------------------------------------------------
// Launch
// ---------------------------------------------------------------------------
extern "C" void kernel_launch(void* const* d_in, const int* in_sizes, int n_in,
                              void* d_out, int out_size)
{
    const float* x  = (const float*)d_in[0];
    const float* wt = (const float*)d_in[1];
    const float* bt = (const float*)d_in[2];
    const float* wp = (const float*)d_in[3];
    const float* bp = (const float*)d_in[4];
    const float* wg = (const float*)d_in[5];
    const float* bg = (const float*)d_in[6];
    const float* wo = (const float*)d_in[7];
    const float* bo = (const float*)d_in[8];
    float* y = (float*)d_out;

    cudaFuncSetAttribute(kfa2, cudaFuncAttributeMaxDynamicSharedMemorySize,
                         DSM_BYTES);

    kprep_w  <<<384, 256>>>(wt, wp, wg);
    kprep_wo <<<128, 256>>>(wo);
    kprep_x  <<<dim3(NN / 32, CC / 32, BB), 256>>>(x);
    kproj_m  <<<dim3(NTILES, 3, BB), 256>>>(bt, bp, bg);
    kfa2     <<<dim3(NTILES, BB), 256, DSM_BYTES>>>();
    kfinal_m <<<dim3(NTILES, 2, BB), 256>>>(x, bo, y);
}